// round 5
// baseline (speedup 1.0000x reference)
#include <cuda_runtime.h>

// SSIM loss, fully fused one-kernel version with f32x2 packed math.
// img1, img2: [32,3,512,512] fp32. Output: scalar fp32 = 1 - mean(ssim_map).
//
// Planes: 0=E[x], 1=E[y], 2=E[x2], 3=E[y2], 4=E[xy].
// Planes (0,1) and (2,3) are processed as f32x2 pairs end-to-end:
// packed vertical ring accumulators -> interleaved float2 smem staging ->
// packed horizontal conv. Plane 4 stays scalar (FFMA-imm weights).

#define HW       512
#define NPLANES  96
#define BAND     44
#define NBANDS   12
#define NBLK     (NBANDS * NPLANES)   // 1152
#define VB       528
// dynamic smem: AB[2][4][VB] float2 | CD[2][4][VB] float2 | E[2][4][VB] float
#define AB_BYTES (2 * 4 * VB * 8)     // 33792
#define CD_OFF   AB_BYTES
#define E_OFF    (2 * AB_BYTES)       // 67584
#define SMEM_DYN (E_OFF + 2 * 4 * VB * 4)   // 84480

typedef unsigned long long ull;

namespace {
constexpr double G_[6] = {0.0038659201595884, 0.0285655007845504,
                          0.1353352832366127, 0.4111122905071874,
                          0.8007374029168081, 1.0};
constexpr double GSUM = 2.0*(G_[0]+G_[1]+G_[2]+G_[3]+G_[4]) + 1.0;
constexpr float gwf(int j){ return (float)(G_[j < 6 ? j : 10 - j] / GSUM); }
}

__device__ constexpr float GW[11] = {
    gwf(0), gwf(1), gwf(2), gwf(3), gwf(4), gwf(5),
    gwf(6), gwf(7), gwf(8), gwf(9), gwf(10)};

__device__ float    g_part[NBLK];
__device__ unsigned g_count = 0;

__device__ __forceinline__ ull pack2(float a, float b) {
    ull r; asm("mov.b64 %0, {%1, %2};" : "=l"(r) : "f"(a), "f"(b)); return r;
}
__device__ __forceinline__ void unpack2(float& a, float& b, ull v) {
    asm("mov.b64 {%0, %1}, %2;" : "=f"(a), "=f"(b) : "l"(v));
}
__device__ __forceinline__ ull fma2(ull a, ull b, ull c) {
    ull d; asm("fma.rn.f32x2 %0, %1, %2, %3;" : "=l"(d) : "l"(a), "l"(b), "l"(c));
    return d;
}
__device__ __forceinline__ ull mul2(ull a, ull b) {
    ull d; asm("mul.rn.f32x2 %0, %1, %2;" : "=l"(d) : "l"(a), "l"(b)); return d;
}

// Deposit j of an ingested row (ring phase PH) -> slot (PH+j+6)%11, belongs
// to output row o = r + j - 5. JMIN masks prologue deposits (only o >= o0).
template<int PH, int JMIN>
__device__ __forceinline__ void ingest2(ull (&A01)[11], ull (&A23)[11],
                                        float (&A4)[11], const ull (&WP)[6],
                                        float v1, float v2)
{
    const ull   P01 = pack2(v1, v2);
    const ull   P23 = mul2(P01, P01);
    const float q4  = v1 * v2;
#pragma unroll
    for (int j = JMIN; j < 11; ++j) {
        const int s  = (PH + j + 6) % 11;
        const int wi = j < 6 ? j : 10 - j;
        A01[s] = fma2(WP[wi], P01, A01[s]);
        A23[s] = fma2(WP[wi], P23, A23[s]);
        A4[s]  = fmaf(GW[j], q4, A4[s]);
    }
}

// Packed 11-tap horizontal conv, 4 adjacent outputs; base = pair index cb.
__device__ __forceinline__ void hconv2(const ull* base, const ull (&WP)[6],
                                       ull (&acc)[4])
{
    ull v[14];
    const ulonglong2* q = (const ulonglong2*)base;
#pragma unroll
    for (int t = 0; t < 7; ++t) { ulonglong2 u = q[t]; v[2*t] = u.x; v[2*t+1] = u.y; }
#pragma unroll
    for (int i = 0; i < 4; ++i) {
        ull s = mul2(WP[0], v[i]);
#pragma unroll
        for (int k = 1; k < 11; ++k) s = fma2(WP[k < 6 ? k : 10 - k], v[i + k], s);
        acc[i] = s;
    }
}

__global__ __launch_bounds__(512, 1)
void ssim_main(const float* __restrict__ img1, const float* __restrict__ img2,
               float* __restrict__ out)
{
    extern __shared__ char dynraw[];
    float2* AB = (float2*)dynraw;             // [b][s][VB]
    float2* CD = (float2*)(dynraw + CD_OFF);
    float*  Ee = (float*)(dynraw + E_OFF);
#define AB_AT(B, S) (AB + ((B) * 4 + (S)) * VB)
#define CD_AT(B, S) (CD + ((B) * 4 + (S)) * VB)
#define E_AT(B, S)  (Ee + ((B) * 4 + (S)) * VB)

    const int c     = threadIdx.x;
    const int band  = blockIdx.x;
    const int plane = blockIdx.y;
    const int o0    = band * BAND;
    const float* __restrict__ p1 = img1 + (size_t)plane * HW * HW;
    const float* __restrict__ p2 = img2 + (size_t)plane * HW * HW;

    __shared__ float  red[16];
    __shared__ double sd[512];
    __shared__ int    amLast;

    // packed weights (6 distinct, symmetric kernel)
    ull WP[6];
#pragma unroll
    for (int k = 0; k < 6; ++k) WP[k] = pack2(GW[k], GW[k]);

    // one-time zero of column borders (emits only touch [5,516])
#pragma unroll
    for (int b = 0; b < 2; ++b)
#pragma unroll
        for (int s = 0; s < 4; ++s) {
            if (c < 5) {
                AB_AT(b, s)[c] = make_float2(0.f, 0.f);
                CD_AT(b, s)[c] = make_float2(0.f, 0.f);
                E_AT(b, s)[c]  = 0.f;
            }
            if (c >= 501) {
                AB_AT(b, s)[c + 16] = make_float2(0.f, 0.f);
                CD_AT(b, s)[c + 16] = make_float2(0.f, 0.f);
                E_AT(b, s)[c + 16]  = 0.f;
            }
        }

    ull   a01[11], a23[11];
    float a4[11];
#pragma unroll
    for (int j = 0; j < 11; ++j) { a01[j] = 0ull; a23[j] = 0ull; a4[j] = 0.f; }

    __syncthreads();

    // ── prologue: rows o0-5 .. o0+4, JMIN = 10-i masking ──
#define PROLOG(i) {                                                          \
        const int  r_  = o0 - 5 + (i);                                       \
        const bool ok_ = (unsigned)r_ < (unsigned)HW;                        \
        const float v1_ = ok_ ? __ldg(&p1[(size_t)r_ * HW + c]) : 0.f;       \
        const float v2_ = ok_ ? __ldg(&p2[(size_t)r_ * HW + c]) : 0.f;       \
        ingest2<((i) + 6) % 11, 10 - (i)>(a01, a23, a4, WP, v1_, v2_); }
    PROLOG(0) PROLOG(1) PROLOG(2) PROLOG(3) PROLOG(4)
    PROLOG(5) PROLOG(6) PROLOG(7) PROLOG(8) PROLOG(9)
#undef PROLOG

    // prefetch banks: bank (G+1)&1 holds ingest rows for group G+1
    float nv1[2][4], nv2[2][4];
#define LOADS(G) {                                                           \
        _Pragma("unroll")                                                    \
        for (int i = 0; i < 4; ++i) {                                        \
            const int  r_  = o0 + 4 * (G) + 9 + i;                           \
            const bool ok_ = r_ < HW;                                        \
            nv1[((G) + 1) & 1][i] = ok_ ? __ldg(&p1[(size_t)r_ * HW + c]) : 0.f; \
            nv2[((G) + 1) & 1][i] = ok_ ? __ldg(&p2[(size_t)r_ * HW + c]) : 0.f; \
        } }

    // ingest + emit sub-row i of group G: row o0+4G+5+i, slot (4G+i)%11
#define ING(G, i) {                                                          \
        ingest2<((4 * (G) + (i)) + 5) % 11, 0>(a01, a23, a4, WP,             \
                                               nv1[(G) & 1][(i)],            \
                                               nv2[(G) & 1][(i)]);           \
        const int sl_ = (4 * (G) + (i)) % 11;                                \
        ((ull*)AB_AT((G) & 1, (i)))[c + 5] = a01[sl_];                       \
        ((ull*)CD_AT((G) & 1, (i)))[c + 5] = a23[sl_];                       \
        E_AT((G) & 1, (i))[c + 5]          = a4[sl_];                        \
        a01[sl_] = 0ull; a23[sl_] = 0ull; a4[sl_] = 0.f; }

    float lsum = 0.f;
    const int rr = c >> 7;            // horizontal: row within group
    const int cq = c & 127;           // horizontal: float4 index
    const int cb = cq << 2;           // horizontal: column / pair base

    // horizontal conv + SSIM for group G out of buffer B
#define HSTEP(G, B) {                                                        \
        ull accAB[4], accCD[4];                                              \
        hconv2((const ull*)AB_AT(B, rr) + cb, WP, accAB);                    \
        hconv2((const ull*)CD_AT(B, rr) + cb, WP, accCD);                    \
        float vE[16];                                                        \
        {                                                                    \
            const float4* qe = (const float4*)E_AT(B, rr) + cq;              \
            _Pragma("unroll")                                                \
            for (int t = 0; t < 4; ++t) {                                    \
                const float4 u = qe[t];                                      \
                vE[4*t] = u.x; vE[4*t+1] = u.y; vE[4*t+2] = u.z; vE[4*t+3] = u.w; \
            }                                                                \
        }                                                                    \
        const int o = o0 + 4 * (G) + rr;                                     \
        if (o < HW) {                                                        \
            _Pragma("unroll")                                                \
            for (int i = 0; i < 4; ++i) {                                    \
                float sE = 0.f;                                              \
                _Pragma("unroll")                                            \
                for (int k = 0; k < 11; ++k) sE = fmaf(GW[k], vE[i + k], sE);\
                float m1, m2, s11r, s22r;                                    \
                unpack2(m1, m2, accAB[i]);                                   \
                unpack2(s11r, s22r, accCD[i]);                               \
                const float C1 = 1e-4f, C2 = 9e-4f;                          \
                const float mu12 = m1 * m2;                                  \
                const float m1s  = m1 * m1;                                  \
                const float m2s  = m2 * m2;                                  \
                const float Anum = 2.f * mu12 + C1;                          \
                const float Bnum = 2.f * (sE - mu12) + C2;                   \
                const float Cden = m1s + m2s + C1;                           \
                const float Dden = (s11r - m1s) + (s22r - m2s) + C2;         \
                lsum += __fdividef(Anum * Bnum, Cden * Dden);                \
            }                                                                \
        } }

    // bank 0 <- ingest rows of group 0 (o0+5..o0+8)
    LOADS(-1)
    LOADS(0)
    ING(0, 0) ING(0, 1) ING(0, 2) ING(0, 3)

#define GBODY(G) {                                                           \
        __syncthreads();                                                     \
        if ((G) < 10) { LOADS(G) }                                           \
        HSTEP((G) - 1, ((G) - 1) & 1)                                        \
        ING(G, 0) ING(G, 1) ING(G, 2) ING(G, 3) }
    GBODY(1) GBODY(2) GBODY(3) GBODY(4) GBODY(5)
    GBODY(6) GBODY(7) GBODY(8) GBODY(9) GBODY(10)
#undef GBODY

    __syncthreads();
    HSTEP(10, 0)

#undef HSTEP
#undef ING
#undef LOADS
#undef AB_AT
#undef CD_AT
#undef E_AT

    // ── block reduction ──
    float v = lsum;
#pragma unroll
    for (int off = 16; off; off >>= 1)
        v += __shfl_xor_sync(0xFFFFFFFFu, v, off);
    if ((c & 31) == 0) red[c >> 5] = v;
    __syncthreads();

    if (c == 0) {
        float bs = 0.f;
#pragma unroll
        for (int w = 0; w < 16; ++w) bs += red[w];
        g_part[plane * NBANDS + band] = bs;
        __threadfence();
        const unsigned t = atomicAdd(&g_count, 1u);
        amLast = (t == NBLK - 1);
    }
    __syncthreads();

    if (amLast) {
        __threadfence();
        double s = 0.0;
        for (int i = c; i < NBLK; i += 512) s += (double)g_part[i];
        sd[c] = s;
        __syncthreads();
#pragma unroll
        for (int k = 256; k > 0; k >>= 1) {
            if (c < k) sd[c] += sd[c + k];
            __syncthreads();
        }
        if (c == 0) {
            out[0]  = (float)(1.0 - sd[0] / 25165824.0);  // 32*3*512*512
            g_count = 0;                                   // reset for replay
        }
    }
}

extern "C" void kernel_launch(void* const* d_in, const int* in_sizes, int n_in,
                              void* d_out, int out_size)
{
    (void)in_sizes; (void)n_in; (void)out_size;
    const float* img1 = (const float*)d_in[0];
    const float* img2 = (const float*)d_in[1];
    cudaFuncSetAttribute(ssim_main, cudaFuncAttributeMaxDynamicSharedMemorySize,
                         SMEM_DYN);
    dim3 grid(NBANDS, NPLANES);
    ssim_main<<<grid, 512, SMEM_DYN>>>(img1, img2, (float*)d_out);
}

// round 6
// speedup vs baseline: 1.0596x; 1.0596x over previous
#include <cuda_runtime.h>

// SSIM loss, fully fused one-kernel version (scalar FFMA-imm everywhere).
// img1, img2: [32,3,512,512] fp32. Output: scalar fp32 = 1 - mean(ssim_map).
//
// Per block: one (plane, 44-row band), 512 threads.
// Vertical 11-tap conv via 11-phase register accumulator ring (1 col/thread),
// 4-row groups into double-buffered smem; horizontal 11-tap conv + SSIM is
// 4 px/thread with per-plane software-pipelined LDS.128 loads.

#define HW       512
#define NPLANES  96
#define BAND     44
#define NBANDS   12
#define NBLK     (NBANDS * NPLANES)   // 1152
#define VB       528
#define VB4      (VB / 4)
#define SMEM_DYN (2 * 5 * 4 * VB4 * 16)   // 84480 bytes

namespace {
constexpr double G_[6] = {0.0038659201595884, 0.0285655007845504,
                          0.1353352832366127, 0.4111122905071874,
                          0.8007374029168081, 1.0};
constexpr double GSUM = 2.0*(G_[0]+G_[1]+G_[2]+G_[3]+G_[4]) + 1.0;
constexpr float gwf(int j){ return (float)(G_[j < 6 ? j : 10 - j] / GSUM); }
}

__device__ constexpr float GW[11] = {
    gwf(0), gwf(1), gwf(2), gwf(3), gwf(4), gwf(5),
    gwf(6), gwf(7), gwf(8), gwf(9), gwf(10)};

__device__ float    g_part[NBLK];
__device__ unsigned g_count = 0;

// Deposit j of an ingested row (ring phase PH) -> slot (PH+j+6)%11, belonging
// to output row o = r + j - 5. JMIN masks prologue deposits (only o >= o0).
// j == 10 is always the FIRST write to its slot since that slot's emit
// (slot (T+10)%11 was emitted at step T-1; in the prologue, step i's j=10 is
// the first-ever touch of slot i) -> plain MUL, no zero-init needed anywhere.
template<int PH, int JMIN>
__device__ __forceinline__ void ingest(float (&A)[5][11], float v1, float v2)
{
    const float q2 = v1 * v1;
    const float q3 = v2 * v2;
    const float q4 = v1 * v2;
#pragma unroll
    for (int j = JMIN; j < 11; ++j) {
        const int   s = (PH + j + 6) % 11;
        const float w = GW[j];
        if (j == 10) {
            A[0][s] = w * v1;
            A[1][s] = w * v2;
            A[2][s] = w * q2;
            A[3][s] = w * q3;
            A[4][s] = w * q4;
        } else {
            A[0][s] = fmaf(w, v1, A[0][s]);
            A[1][s] = fmaf(w, v2, A[1][s]);
            A[2][s] = fmaf(w, q2, A[2][s]);
            A[3][s] = fmaf(w, q3, A[3][s]);
            A[4][s] = fmaf(w, q4, A[4][s]);
        }
    }
}

// Load 16 consecutive floats (4 x LDS.128) of one staging plane row.
__device__ __forceinline__ void hload(const float4* q, float (&v)[16])
{
    const float4 a = q[0], b = q[1], c4 = q[2], d = q[3];
    v[0]=a.x;  v[1]=a.y;  v[2]=a.z;  v[3]=a.w;
    v[4]=b.x;  v[5]=b.y;  v[6]=b.z;  v[7]=b.w;
    v[8]=c4.x; v[9]=c4.y; v[10]=c4.z; v[11]=c4.w;
    v[12]=d.x; v[13]=d.y; v[14]=d.z; v[15]=d.w;
}

// 11-tap horizontal conv for 4 adjacent outputs; optionally accumulate.
template<bool ACC>
__device__ __forceinline__ void hconv(const float (&v)[16], float (&r)[4])
{
#pragma unroll
    for (int i = 0; i < 4; ++i) {
        float s = ACC ? fmaf(GW[0], v[i], r[i]) : GW[0] * v[i];
#pragma unroll
        for (int k = 1; k < 11; ++k) s = fmaf(GW[k], v[i + k], s);
        r[i] = s;
    }
}

__global__ __launch_bounds__(512, 1)
void ssim_main(const float* __restrict__ img1, const float* __restrict__ img2,
               float* __restrict__ out)
{
    extern __shared__ float4 dynbuf[];   // [2][5][4][VB4]
#define VBUF(B, P, S) ((float*)(dynbuf + (((B)*5 + (P))*4 + (S)) * VB4))

    const int c     = threadIdx.x;
    const int band  = blockIdx.x;
    const int plane = blockIdx.y;
    const int o0    = band * BAND;
    const float* __restrict__ p1 = img1 + (size_t)plane * HW * HW;
    const float* __restrict__ p2 = img2 + (size_t)plane * HW * HW;

    __shared__ float  red[16];
    __shared__ double sd[512];
    __shared__ int    amLast;

    // one-time zero of column borders (emits only touch [5,516])
#pragma unroll
    for (int b = 0; b < 2; ++b)
#pragma unroll
        for (int p = 0; p < 5; ++p)
#pragma unroll
            for (int s = 0; s < 4; ++s) {
                float* bb = VBUF(b, p, s);
                if (c < 5)    bb[c] = 0.f;
                if (c >= 501) bb[c + 16] = 0.f;   // 517..527
            }

    float acc[5][11];   // no init needed: first touch of every slot is a MUL

    __syncthreads();

    // ── prologue: rows o0-5 .. o0+4, JMIN = 10-i masking ──
#define PROLOG(i) {                                                          \
        const int  r_  = o0 - 5 + (i);                                       \
        const bool ok_ = (unsigned)r_ < (unsigned)HW;                        \
        const float v1_ = ok_ ? __ldg(&p1[(size_t)r_ * HW + c]) : 0.f;       \
        const float v2_ = ok_ ? __ldg(&p2[(size_t)r_ * HW + c]) : 0.f;       \
        ingest<((i) + 6) % 11, 10 - (i)>(acc, v1_, v2_); }
    PROLOG(0) PROLOG(1) PROLOG(2) PROLOG(3) PROLOG(4)
    PROLOG(5) PROLOG(6) PROLOG(7) PROLOG(8) PROLOG(9)
#undef PROLOG

    // prefetch banks: bank (G+1)&1 holds ingest rows for group G+1
    float nv1[2][4], nv2[2][4];
#define LOADS(G) {                                                           \
        _Pragma("unroll")                                                    \
        for (int i = 0; i < 4; ++i) {                                        \
            const int  r_  = o0 + 4 * (G) + 9 + i;                           \
            const bool ok_ = r_ < HW;                                        \
            nv1[((G) + 1) & 1][i] = ok_ ? __ldg(&p1[(size_t)r_ * HW + c]) : 0.f; \
            nv2[((G) + 1) & 1][i] = ok_ ? __ldg(&p2[(size_t)r_ * HW + c]) : 0.f; \
        } }

    // ingest + emit sub-row i of group G: row o0+4G+5+i, slot (4G+i)%11
#define ING(G, i) {                                                          \
        ingest<((4 * (G) + (i)) + 5) % 11, 0>(acc, nv1[(G) & 1][(i)],        \
                                              nv2[(G) & 1][(i)]);            \
        _Pragma("unroll")                                                    \
        for (int p = 0; p < 5; ++p)                                          \
            VBUF((G) & 1, p, (i))[c + 5] = acc[p][(4 * (G) + (i)) % 11]; }

    float lsum = 0.f;
    const int rr = c >> 7;            // horizontal: row within group
    const int cq = c & 127;           // horizontal: float4 index

    // horizontal conv + SSIM for group G out of buffer B.
    // Per-plane software pipeline: issue plane p+1 loads before plane p FMAs.
#define HSTEP(G, B) {                                                        \
        float v0[16], v1v[16];                                               \
        hload((const float4*)VBUF(B, 0, rr) + cq, v0);                       \
        hload((const float4*)VBUF(B, 1, rr) + cq, v1v);                      \
        float m1[4]; hconv<false>(v0, m1);                                   \
        hload((const float4*)VBUF(B, 2, rr) + cq, v0);                       \
        float m2[4]; hconv<false>(v1v, m2);                                  \
        hload((const float4*)VBUF(B, 3, rr) + cq, v1v);                      \
        float ssum[4]; hconv<false>(v0, ssum);                               \
        hload((const float4*)VBUF(B, 4, rr) + cq, v0);                       \
        hconv<true>(v1v, ssum);          /* ssum = s11 + s22 */              \
        float e12[4]; hconv<false>(v0, e12);                                 \
        const int o = o0 + 4 * (G) + rr;                                     \
        if (o < HW) {                                                        \
            _Pragma("unroll")                                                \
            for (int i = 0; i < 4; ++i) {                                    \
                const float C1 = 1e-4f, C2 = 9e-4f;                          \
                const float mu12 = m1[i] * m2[i];                            \
                const float msum = m1[i] * m1[i] + m2[i] * m2[i];            \
                const float Anum = 2.f * mu12 + C1;                          \
                const float Bnum = 2.f * (e12[i] - mu12) + C2;               \
                const float Cden = msum + C1;                                \
                const float Dden = (ssum[i] - msum) + C2;                    \
                lsum += __fdividef(Anum * Bnum, Cden * Dden);                \
            }                                                                \
        } }

    // bank 0 <- ingest rows of group 0 (o0+5..o0+8)
    LOADS(-1)
    LOADS(0)
    ING(0, 0) ING(0, 1) ING(0, 2) ING(0, 3)

#define GBODY(G) {                                                           \
        __syncthreads();                                                     \
        if ((G) < 10) { LOADS(G) }                                           \
        HSTEP((G) - 1, ((G) - 1) & 1)                                        \
        ING(G, 0) ING(G, 1) ING(G, 2) ING(G, 3) }
    GBODY(1) GBODY(2) GBODY(3) GBODY(4) GBODY(5)
    GBODY(6) GBODY(7) GBODY(8) GBODY(9) GBODY(10)
#undef GBODY

    __syncthreads();
    HSTEP(10, 0)

#undef HSTEP
#undef ING
#undef LOADS
#undef VBUF

    // ── block reduction ──
    float v = lsum;
#pragma unroll
    for (int off = 16; off; off >>= 1)
        v += __shfl_xor_sync(0xFFFFFFFFu, v, off);
    if ((c & 31) == 0) red[c >> 5] = v;
    __syncthreads();

    if (c == 0) {
        float bs = 0.f;
#pragma unroll
        for (int w = 0; w < 16; ++w) bs += red[w];
        g_part[plane * NBANDS + band] = bs;
        __threadfence();
        const unsigned t = atomicAdd(&g_count, 1u);
        amLast = (t == NBLK - 1);
    }
    __syncthreads();

    if (amLast) {
        __threadfence();
        double s = 0.0;
        for (int i = c; i < NBLK; i += 512) s += (double)g_part[i];
        sd[c] = s;
        __syncthreads();
#pragma unroll
        for (int k = 256; k > 0; k >>= 1) {
            if (c < k) sd[c] += sd[c + k];
            __syncthreads();
        }
        if (c == 0) {
            out[0]  = (float)(1.0 - sd[0] / 25165824.0);  // 32*3*512*512
            g_count = 0;                                   // reset for replay
        }
    }
}

extern "C" void kernel_launch(void* const* d_in, const int* in_sizes, int n_in,
                              void* d_out, int out_size)
{
    (void)in_sizes; (void)n_in; (void)out_size;
    const float* img1 = (const float*)d_in[0];
    const float* img2 = (const float*)d_in[1];
    cudaFuncSetAttribute(ssim_main, cudaFuncAttributeMaxDynamicSharedMemorySize,
                         SMEM_DYN);
    dim3 grid(NBANDS, NPLANES);
    ssim_main<<<grid, 512, SMEM_DYN>>>(img1, img2, (float*)d_out);
}

// round 7
// speedup vs baseline: 1.2572x; 1.1865x over previous
#include <cuda_runtime.h>

// SSIM loss, fully fused one-kernel version, 4-plane formulation.
// img1, img2: [32,3,512,512] fp32. Output: scalar fp32 = 1 - mean(ssim_map).
//
// SSIM only needs conv(x), conv(y), conv(x^2 + y^2), conv(x*y): the x^2 and
// y^2 planes are folded BEFORE the convolution (linearity), cutting conv work
// by 20% vs the naive 5-plane form.
//
// Per block: one (plane, 44-row band), 512 threads. Vertical 11-tap conv via
// 11-phase register accumulator ring (1 col/thread), 4-row groups into
// double-buffered smem; horizontal 11-tap conv + SSIM at 4 px/thread (LDS.128).

#define HW       512
#define NPLANES  96
#define BAND     44
#define NBANDS   12
#define NBLK     (NBANDS * NPLANES)   // 1152
#define VB       528
#define VB4      (VB / 4)
#define SMEM_DYN (2 * 4 * 4 * VB4 * 16)   // 67584 bytes

namespace {
constexpr double G_[6] = {0.0038659201595884, 0.0285655007845504,
                          0.1353352832366127, 0.4111122905071874,
                          0.8007374029168081, 1.0};
constexpr double GSUM = 2.0*(G_[0]+G_[1]+G_[2]+G_[3]+G_[4]) + 1.0;
constexpr float gwf(int j){ return (float)(G_[j < 6 ? j : 10 - j] / GSUM); }
}

__device__ constexpr float GW[11] = {
    gwf(0), gwf(1), gwf(2), gwf(3), gwf(4), gwf(5),
    gwf(6), gwf(7), gwf(8), gwf(9), gwf(10)};

__device__ float    g_part[NBLK];
__device__ unsigned g_count = 0;

// Deposit j of an ingested row (ring phase PH) -> slot (PH+j+6)%11, belonging
// to output row o = r + j - 5. JMIN masks prologue deposits (only o >= o0).
// j == 10 is always the FIRST write to its slot since that slot's emit
// (validated in R6: identical rel_err) -> plain MUL, no ring init anywhere.
// Planes: 0 = x, 1 = y, 2 = x^2 + y^2, 3 = x*y.
template<int PH, int JMIN>
__device__ __forceinline__ void ingest(float (&A)[4][11], float v1, float v2)
{
    const float q2  = v1 * v1;
    const float q23 = fmaf(v2, v2, q2);
    const float q4  = v1 * v2;
#pragma unroll
    for (int j = JMIN; j < 11; ++j) {
        const int   s = (PH + j + 6) % 11;
        const float w = GW[j];
        if (j == 10) {
            A[0][s] = w * v1;
            A[1][s] = w * v2;
            A[2][s] = w * q23;
            A[3][s] = w * q4;
        } else {
            A[0][s] = fmaf(w, v1,  A[0][s]);
            A[1][s] = fmaf(w, v2,  A[1][s]);
            A[2][s] = fmaf(w, q23, A[2][s]);
            A[3][s] = fmaf(w, q4,  A[3][s]);
        }
    }
}

__global__ __launch_bounds__(512, 1)
void ssim_main(const float* __restrict__ img1, const float* __restrict__ img2,
               float* __restrict__ out)
{
    extern __shared__ float4 dynbuf[];   // [2][4][4][VB4]
#define VBUF(B, P, S) ((float*)(dynbuf + (((B)*4 + (P))*4 + (S)) * VB4))

    const int c     = threadIdx.x;
    const int band  = blockIdx.x;
    const int plane = blockIdx.y;
    const int o0    = band * BAND;
    const float* __restrict__ p1 = img1 + (size_t)plane * HW * HW;
    const float* __restrict__ p2 = img2 + (size_t)plane * HW * HW;

    __shared__ float  red[16];
    __shared__ double sd[512];
    __shared__ int    amLast;

    // one-time zero of column borders (emits only touch [5,516])
#pragma unroll
    for (int b = 0; b < 2; ++b)
#pragma unroll
        for (int p = 0; p < 4; ++p)
#pragma unroll
            for (int s = 0; s < 4; ++s) {
                float* bb = VBUF(b, p, s);
                if (c < 5)    bb[c] = 0.f;
                if (c >= 501) bb[c + 16] = 0.f;   // 517..527
            }

    float acc[4][11];   // no init: first touch of every slot is the j==10 MUL

    __syncthreads();

    // ── prologue: rows o0-5 .. o0+4, JMIN = 10-i masking ──
#define PROLOG(i) {                                                          \
        const int  r_  = o0 - 5 + (i);                                       \
        const bool ok_ = (unsigned)r_ < (unsigned)HW;                        \
        const float v1_ = ok_ ? __ldg(&p1[(size_t)r_ * HW + c]) : 0.f;       \
        const float v2_ = ok_ ? __ldg(&p2[(size_t)r_ * HW + c]) : 0.f;       \
        ingest<((i) + 6) % 11, 10 - (i)>(acc, v1_, v2_); }
    PROLOG(0) PROLOG(1) PROLOG(2) PROLOG(3) PROLOG(4)
    PROLOG(5) PROLOG(6) PROLOG(7) PROLOG(8) PROLOG(9)
#undef PROLOG

    // prefetch banks: bank (G+1)&1 holds ingest rows for group G+1
    float nv1[2][4], nv2[2][4];
#define LOADS(G) {                                                           \
        _Pragma("unroll")                                                    \
        for (int i = 0; i < 4; ++i) {                                        \
            const int  r_  = o0 + 4 * (G) + 9 + i;                           \
            const bool ok_ = r_ < HW;                                        \
            nv1[((G) + 1) & 1][i] = ok_ ? __ldg(&p1[(size_t)r_ * HW + c]) : 0.f; \
            nv2[((G) + 1) & 1][i] = ok_ ? __ldg(&p2[(size_t)r_ * HW + c]) : 0.f; \
        } }

    // ingest + emit sub-row i of group G: row o0+4G+5+i, slot (4G+i)%11
#define ING(G, i) {                                                          \
        ingest<((4 * (G) + (i)) + 5) % 11, 0>(acc, nv1[(G) & 1][(i)],        \
                                              nv2[(G) & 1][(i)]);            \
        _Pragma("unroll")                                                    \
        for (int p = 0; p < 4; ++p)                                          \
            VBUF((G) & 1, p, (i))[c + 5] = acc[p][(4 * (G) + (i)) % 11]; }

    float lsum = 0.f;
    const int rr = c >> 7;            // horizontal: row within group
    const int cq = c & 127;           // horizontal: float4 index

    // horizontal conv + SSIM for group G out of buffer B (R4 shape: flat
    // per-plane load+conv blocks, ptxas schedules the overlap)
#define HSTEP(G, B) {                                                        \
        float hr[4][4];                                                      \
        _Pragma("unroll")                                                    \
        for (int p = 0; p < 4; ++p) {                                        \
            const float4* q = dynbuf + (((B)*4 + p)*4 + rr) * VB4 + cq;      \
            const float4 A = q[0], Bv = q[1], Cv = q[2], D = q[3];           \
            const float v[16] = {A.x, A.y, A.z, A.w,  Bv.x, Bv.y, Bv.z, Bv.w,\
                                 Cv.x, Cv.y, Cv.z, Cv.w,  D.x, D.y, D.z, D.w};\
            _Pragma("unroll")                                                \
            for (int i = 0; i < 4; ++i) {                                    \
                float s = GW[0] * v[i];                                      \
                _Pragma("unroll")                                            \
                for (int k = 1; k < 11; ++k) s = fmaf(GW[k], v[i + k], s);   \
                hr[p][i] = s;                                                \
            }                                                                \
        }                                                                    \
        const int o = o0 + 4 * (G) + rr;                                     \
        if (o < HW) {                                                        \
            _Pragma("unroll")                                                \
            for (int i = 0; i < 4; ++i) {                                    \
                const float C1 = 1e-4f, C2 = 9e-4f;                          \
                const float m1 = hr[0][i], m2 = hr[1][i];                    \
                const float mu12 = m1 * m2;                                  \
                const float msum = fmaf(m1, m1, m2 * m2);                    \
                const float Anum = 2.f * mu12 + C1;                          \
                const float Bnum = 2.f * (hr[3][i] - mu12) + C2;             \
                const float Cden = msum + C1;                                \
                const float Dden = (hr[2][i] - msum) + C2;                   \
                lsum += __fdividef(Anum * Bnum, Cden * Dden);                \
            }                                                                \
        } }

    // bank 0 <- ingest rows of group 0 (o0+5..o0+8)
    LOADS(-1)
    LOADS(0)
    ING(0, 0) ING(0, 1) ING(0, 2) ING(0, 3)

#define GBODY(G) {                                                           \
        __syncthreads();                                                     \
        if ((G) < 10) { LOADS(G) }                                           \
        HSTEP((G) - 1, ((G) - 1) & 1)                                        \
        ING(G, 0) ING(G, 1) ING(G, 2) ING(G, 3) }
    GBODY(1) GBODY(2) GBODY(3) GBODY(4) GBODY(5)
    GBODY(6) GBODY(7) GBODY(8) GBODY(9) GBODY(10)
#undef GBODY

    __syncthreads();
    HSTEP(10, 0)

#undef HSTEP
#undef ING
#undef LOADS
#undef VBUF

    // ── block reduction ──
    float v = lsum;
#pragma unroll
    for (int off = 16; off; off >>= 1)
        v += __shfl_xor_sync(0xFFFFFFFFu, v, off);
    if ((c & 31) == 0) red[c >> 5] = v;
    __syncthreads();

    if (c == 0) {
        float bs = 0.f;
#pragma unroll
        for (int w = 0; w < 16; ++w) bs += red[w];
        g_part[plane * NBANDS + band] = bs;
        __threadfence();
        const unsigned t = atomicAdd(&g_count, 1u);
        amLast = (t == NBLK - 1);
    }
    __syncthreads();

    if (amLast) {
        __threadfence();
        double s = 0.0;
        for (int i = c; i < NBLK; i += 512) s += (double)g_part[i];
        sd[c] = s;
        __syncthreads();
#pragma unroll
        for (int k = 256; k > 0; k >>= 1) {
            if (c < k) sd[c] += sd[c + k];
            __syncthreads();
        }
        if (c == 0) {
            out[0]  = (float)(1.0 - sd[0] / 25165824.0);  // 32*3*512*512
            g_count = 0;                                   // reset for replay
        }
    }
}

extern "C" void kernel_launch(void* const* d_in, const int* in_sizes, int n_in,
                              void* d_out, int out_size)
{
    (void)in_sizes; (void)n_in; (void)out_size;
    const float* img1 = (const float*)d_in[0];
    const float* img2 = (const float*)d_in[1];
    cudaFuncSetAttribute(ssim_main, cudaFuncAttributeMaxDynamicSharedMemorySize,
                         SMEM_DYN);
    dim3 grid(NBANDS, NPLANES);
    ssim_main<<<grid, 512, SMEM_DYN>>>(img1, img2, (float*)d_out);
}